// round 1
// baseline (speedup 1.0000x reference)
#include <cuda_runtime.h>
#include <cuda_bf16.h>

#define TT 1024
#define BB 4096
#define GB 16                  // b-partitions for histogram grid
#define MAIN_BLOCKS 1024
#define MAIN_THREADS 256
#define NEGBIG (-1.0e30f)

// ---- device scratch (no allocations allowed) ----
__device__ int   g_counts[TT * 3];        // zero-init; reset by invw_kernel each run
__device__ float g_invw[TT * 3];          // 1/(3*counts)
__device__ float g_bsum[MAIN_BLOCKS];     // per-block partial sums

// ======================= special functions =======================
// Stirling lgamma for y >= 5 (abs err < 1e-7 at y=5)
__device__ __forceinline__ float stirl_lg(float y) {
    float r  = __fdividef(1.0f, y);
    float L  = __logf(y);
    float r2 = r * r;
    float inner = fmaf(r2, fmaf(r2, 7.9365079e-4f, -2.7777778e-3f), 8.3333333e-2f);
    return fmaf(y - 0.5f, L, fmaf(r, inner, 0.91893853f - y));
}

// Stirling lgamma + digamma for y >= 5
__device__ __forceinline__ void stirl_both(float y, float& lg, float& ps) {
    float r  = __fdividef(1.0f, y);
    float L  = __logf(y);
    float r2 = r * r;
    float il = fmaf(r2, fmaf(r2, 7.9365079e-4f, -2.7777778e-3f), 8.3333333e-2f);
    lg = fmaf(y - 0.5f, L, fmaf(r, il, 0.91893853f - y));
    // psi(y) = L - r/2 - r2*(1/12 - r2*(1/120 - r2/252))
    float w  = fmaf(r2, 3.96825397e-3f, -8.3333333e-3f);   // r2/252 - 1/120
    ps = fmaf(-r2, fmaf(r2, w, 8.3333333e-2f), fmaf(-0.5f, r, L));
}

// KL( Beta(ta,tb) || Beta(pa,pb) ) with sp=tc+2, sq=pc+2 identities.
// Inputs: raw logits l0,l1 and sanitized target params tw,tc.
__device__ __forceinline__ float elem_kl(float l0, float l1, float tw, float tcv) {
    // predictions: sigmoid, scale
    float pw  = __fdividef(1.0f, 1.0f + __expf(-l0));
    float pcs = __fdividef(1.0f, 1.0f + __expf(-l1));
    float pc  = fmaf(pcs, 1023.0f, 5.0f);          // (T-1) = 1023

    float sp = tcv + 2.0f;                          // = ta + tb exactly
    float sq = pc + 2.0f;                           // = pa + pb exactly
    float ta = fmaf(tcv, tw, 1.0f);
    float tb = sp - ta;
    float pa = fmaf(pc, pw, 1.0f);
    float pb = sq - pa;

    // shift-by-4 products: P(x) = x(x+1)(x+2)(x+3) = u(u+2), u = x(x+3)
    float uta = ta * (ta + 3.0f), Pta = uta * (uta + 2.0f);
    float utb = tb * (tb + 3.0f), Ptb = utb * (utb + 2.0f);
    float upa = pa * (pa + 3.0f), Ppa = upa * (upa + 2.0f);
    float upb = pb * (pb + 3.0f), Ppb = upb * (upb + 2.0f);

    float lgta, psta; stirl_both(ta + 4.0f, lgta, psta);
    psta -= __fdividef(fmaf(2.0f, uta, 2.0f) * fmaf(2.0f, ta, 3.0f), Pta);  // - P'/P
    float lgtb, pstb; stirl_both(tb + 4.0f, lgtb, pstb);
    pstb -= __fdividef(fmaf(2.0f, utb, 2.0f) * fmaf(2.0f, tb, 3.0f), Ptb);
    float lgsp, pssp; stirl_both(sp, lgsp, pssp);   // sp in [7,32]: direct
    float lgpa = stirl_lg(pa + 4.0f);
    float lgpb = stirl_lg(pb + 4.0f);
    float lgsq = stirl_lg(sq);                      // sq in (7,1030): direct

    // combined shift logs: +lnPta +lnPtb -lnPpa -lnPpb
    float logdiff = __logf(Pta * Ptb) - __logf(Ppa * Ppb);

    return (lgpa + lgpb + lgsp) - (lgta + lgtb + lgsq) + logdiff
         + (ta - pa) * psta + (tb - pb) * pstb + (sq - sp) * pssp;
}

// ======================= kernel 1: histogram =======================
// Register-resident per-t class counters; no data-path atomics.
// block (32 t-lanes, 8 b-rows); grid (T/32, GB).
__global__ void hist_kernel(const float* __restrict__ tgt) {
    int t    = blockIdx.x * 32 + threadIdx.x;
    int bend = (blockIdx.y + 1) * (BB / GB);
    int c0 = 0, c1 = 0, c2 = 0;
    for (int b = blockIdx.y * (BB / GB) + threadIdx.y; b < bend; b += 8) {
        float x2 = __ldg(&tgt[((size_t)b * TT + t) * 3 + 2]);
        if (x2 > NEGBIG) {                 // valid iff not -inf (dx in {0,1,2})
            int dx = (int)x2;
            c0 += (dx == 0); c1 += (dx == 1); c2 += (dx == 2);
        }
    }
    __shared__ int sh[3][32];
    if (threadIdx.y == 0) { sh[0][threadIdx.x] = 0; sh[1][threadIdx.x] = 0; sh[2][threadIdx.x] = 0; }
    __syncthreads();
    atomicAdd(&sh[0][threadIdx.x], c0);
    atomicAdd(&sh[1][threadIdx.x], c1);
    atomicAdd(&sh[2][threadIdx.x], c2);
    __syncthreads();
    if (threadIdx.y < 3)
        atomicAdd(&g_counts[t * 3 + threadIdx.y], sh[threadIdx.y][threadIdx.x]);
}

// ======================= kernel 2: inv weights + reset counts =======================
__global__ void invw_kernel() {
    int i = blockIdx.x * blockDim.x + threadIdx.x;
    if (i < TT * 3) {
        int c = g_counts[i];
        g_invw[i] = (c > 0) ? (1.0f / (3.0f * (float)c)) : 0.0f;
        g_counts[i] = 0;                   // ready for next graph replay
    }
}

// ======================= kernel 3: main KL pass =======================
__global__ void __launch_bounds__(MAIN_THREADS)
main_kernel(const float* __restrict__ logits, const float* __restrict__ tgt) {
    const float4* tg4 = reinterpret_cast<const float4*>(tgt);
    const float4* lg4 = reinterpret_cast<const float4*>(logits);
    const int total4 = (BB * TT) / 4;
    const int stride = gridDim.x * blockDim.x;

    float acc = 0.0f;
    for (int g = blockIdx.x * blockDim.x + threadIdx.x; g < total4; g += stride) {
        float4 a = tg4[g * 3 + 0];
        float4 b = tg4[g * 3 + 1];
        float4 c = tg4[g * 3 + 2];
        float4 d = lg4[g * 2 + 0];
        float4 e = lg4[g * 2 + 1];
        float tv[12] = {a.x, a.y, a.z, a.w, b.x, b.y, b.z, b.w, c.x, c.y, c.z, c.w};
        float lv[8]  = {d.x, d.y, d.z, d.w, e.x, e.y, e.z, e.w};
        int t0 = (g * 4) & (TT - 1);
#pragma unroll
        for (int j = 0; j < 4; j++) {
            float x0 = tv[3 * j], x1 = tv[3 * j + 1], x2 = tv[3 * j + 2];
            bool m = (x0 > NEGBIG) && (x1 > NEGBIG) && (x2 > NEGBIG);
            float tw  = m ? x0 : 0.5f;
            float tcv = m ? x1 : 5.0f;
            int   dx  = m ? (int)x2 : 0;
            float kl = elem_kl(lv[2 * j], lv[2 * j + 1], tw, tcv);
            float w  = __ldg(&g_invw[(t0 + j) * 3 + dx]);   // 12KB table: L1/L2 resident
            acc += m ? kl * w : 0.0f;
        }
    }

    // block reduction (deterministic within block)
#pragma unroll
    for (int off = 16; off > 0; off >>= 1)
        acc += __shfl_xor_sync(0xffffffffu, acc, off);
    __shared__ float wsum[MAIN_THREADS / 32];
    int lane = threadIdx.x & 31, wid = threadIdx.x >> 5;
    if (lane == 0) wsum[wid] = acc;
    __syncthreads();
    if (threadIdx.x == 0) {
        float s = 0.0f;
#pragma unroll
        for (int i = 0; i < MAIN_THREADS / 32; i++) s += wsum[i];
        g_bsum[blockIdx.x] = s;
    }
}

// ======================= kernel 4: deterministic finalize =======================
__global__ void finalize_kernel(float* out) {
    __shared__ double sh[256];
    double s = 0.0;
    for (int i = threadIdx.x; i < MAIN_BLOCKS; i += 256) s += (double)g_bsum[i];
    sh[threadIdx.x] = s;
    __syncthreads();
    for (int k = 128; k > 0; k >>= 1) {
        if (threadIdx.x < k) sh[threadIdx.x] += sh[threadIdx.x + k];
        __syncthreads();
    }
    if (threadIdx.x == 0) out[0] = (float)(sh[0] / (double)TT);
}

// ======================= launch =======================
extern "C" void kernel_launch(void* const* d_in, const int* in_sizes, int n_in,
                              void* d_out, int out_size) {
    const float* logits;
    const float* targets;
    if (in_sizes[0] == BB * TT * 2) {          // robust to metadata ordering
        logits  = (const float*)d_in[0];
        targets = (const float*)d_in[1];
    } else {
        logits  = (const float*)d_in[1];
        targets = (const float*)d_in[0];
    }
    float* out = (float*)d_out;

    hist_kernel<<<dim3(TT / 32, GB), dim3(32, 8)>>>(targets);
    invw_kernel<<<(TT * 3 + 255) / 256, 256>>>();
    main_kernel<<<MAIN_BLOCKS, MAIN_THREADS>>>(logits, targets);
    finalize_kernel<<<1, 256>>>(out);
}